// round 11
// baseline (speedup 1.0000x reference)
#include <cuda_runtime.h>
#include <cuda_fp16.h>
#include <cstdint>
#include <cstddef>

#define N_NODES 50000
#define N_EDGES 600000
#define IN_DIM  16
#define HIDDEN  128
#define OUT_DIM 4

typedef __half f16;

// ---------------- device scratch (static: no allocs allowed) ----------------
// Invariants at entry to every kernel_launch call (zero-init at module load;
// re-zeroed in k_fill after consumption): g_deg == 0, g_state == 0.
__device__ int      g_deg[N_NODES];
__device__ unsigned g_state[64];
__device__ int      g_off[N_NODES + 1];
__device__ int      g_pos[N_NODES];
__device__ int      g_csr[N_EDGES];

__device__ float g_agg[(size_t)N_NODES * IN_DIM];      // layer1 agg (f32)
// fp16 hi/lo splits
__device__ f16   g_aggh[(size_t)N_NODES * HIDDEN];
__device__ f16   g_aggl[(size_t)N_NODES * HIDDEN];
__device__ f16   g_h1h[(size_t)N_NODES * HIDDEN];
__device__ f16   g_h1l[(size_t)N_NODES * HIDDEN];
__device__ f16   g_h2h[(size_t)N_NODES * HIDDEN];
__device__ f16   g_h2l[(size_t)N_NODES * HIDDEN];
// W splits: order Wl2, Wr2, Wl3, Wr3
__device__ f16   g_Wh[4][HIDDEN * HIDDEN];
__device__ f16   g_Wl[4][HIDDEN * HIDDEN];

// ---------------- helpers ----------------
__device__ __forceinline__ void hsplit(float x, f16& h, f16& l) {
    h = __float2half_rn(x);
    l = __float2half_rn(x - __half2float(h));
}

__device__ __forceinline__ void mma_f16(float c[4], const uint32_t a[4],
                                        uint32_t b0, uint32_t b1) {
    asm volatile(
        "mma.sync.aligned.m16n8k16.row.col.f32.f16.f16.f32 "
        "{%0,%1,%2,%3}, {%4,%5,%6,%7}, {%8,%9}, {%0,%1,%2,%3};"
        : "+f"(c[0]), "+f"(c[1]), "+f"(c[2]), "+f"(c[3])
        : "r"(a[0]), "r"(a[1]), "r"(a[2]), "r"(a[3]), "r"(b0), "r"(b1));
}

#define LDSM4(r, addr) \
    asm volatile("ldmatrix.sync.aligned.m8n8.x4.shared.b16 {%0,%1,%2,%3}, [%4];" \
        : "=r"((r)[0]), "=r"((r)[1]), "=r"((r)[2]), "=r"((r)[3]) : "r"(addr))
#define LDSM2(r0, r1, addr) \
    asm volatile("ldmatrix.sync.aligned.m8n8.x2.shared.b16 {%0,%1}, [%2];" \
        : "=r"(r0), "=r"(r1) : "r"(addr))
#define CP16(dst, src, sz) \
    asm volatile("cp.async.ca.shared.global [%0], [%1], 16, %2;" \
        :: "r"(dst), "l"(src), "r"(sz))
#define CP_COMMIT() asm volatile("cp.async.commit_group;")
#define CP_WAIT1()  asm volatile("cp.async.wait_group 1;")
#define CP_WAIT0()  asm volatile("cp.async.wait_group 0;")

__device__ __forceinline__ int load_idx(const void* ei, long long pos, int is32) {
    if (is32) return ((const int*)ei)[pos];
    return (int)(((const long long*)ei)[pos]);
}

// Block-local dtype detect: warp 0 scans 64 int64 slots; int32 data misread
// as int64 yields values outside [0, N_NODES) with overwhelming probability.
__device__ __forceinline__ int detect_is32(const void* ei, int tid, int* s_is32) {
    if (tid < 32) {
        const long long* p = (const long long*)ei;
        long long v0 = p[tid];
        long long v1 = p[32 + tid];
        int bad = (v0 < 0 || v0 >= N_NODES || v1 < 0 || v1 >= N_NODES) ? 1 : 0;
        unsigned m = __ballot_sync(0xffffffffu, bad);
        if (tid == 0) *s_is32 = m ? 1 : 0;
    }
    __syncthreads();
    return *s_is32;
}

// ---------------- CSR: count (+ W split folded in), 8 edges/thread ---------
__global__ void k_count(const void* ei,
                        const float* __restrict__ Wl2, const float* __restrict__ Wr2,
                        const float* __restrict__ Wl3, const float* __restrict__ Wr3) {
    __shared__ int s_is32;
    int tid = threadIdx.x;
    int is32 = detect_is32(ei, tid, &s_is32);

    // W split: first 65536 global threads handle one element each
    int gid = blockIdx.x * 256 + tid;
    if (gid < 65536) {
        int w = gid >> 14;
        int e = gid & 16383;
        const float* src = (w == 0) ? Wl2 : (w == 1) ? Wr2 : (w == 2) ? Wl3 : Wr3;
        float v = src[e];
        f16 h, l;
        hsplit(v, h, l);
        g_Wh[w][e] = h;
        g_Wl[w][e] = l;
    }

    int base = blockIdx.x * 2048 + tid;
    int d[8];
    #pragma unroll
    for (int k = 0; k < 8; k++) {
        int e = base + k * 256;
        d[k] = (e < N_EDGES) ? load_idx(ei, (long long)N_EDGES + e, is32) : -1;
    }
    #pragma unroll
    for (int k = 0; k < 8; k++)
        if (d[k] >= 0) atomicAdd(&g_deg[d[k]], 1);
}

// ---------------- single-pass scan with decoupled lookback ----------------
__global__ void k_scan() {
    __shared__ int warp_sums[32];
    __shared__ int s_prev;
    int tid = threadIdx.x;  // 1024
    int bid = blockIdx.x;
    int i = bid * 1024 + tid;
    int v = (i < N_NODES) ? g_deg[i] : 0;
    int x = v;
    #pragma unroll
    for (int d = 1; d < 32; d <<= 1) {
        int y = __shfl_up_sync(0xffffffffu, x, d);
        if ((tid & 31) >= d) x += y;
    }
    if ((tid & 31) == 31) warp_sums[tid >> 5] = x;
    __syncthreads();
    if (tid < 32) {
        int w = warp_sums[tid];
        #pragma unroll
        for (int d = 1; d < 32; d <<= 1) {
            int y = __shfl_up_sync(0xffffffffu, w, d);
            if (tid >= d) w += y;
        }
        warp_sums[tid] = w;
    }
    __syncthreads();
    int excl = x - v + ((tid >= 32) ? warp_sums[(tid >> 5) - 1] : 0);
    int block_total = warp_sums[31];

    if (tid == 0) {
        if (bid == 0) {
            *(volatile unsigned*)&g_state[0] = (2u << 30) | (unsigned)block_total;
            s_prev = 0;
        } else {
            *(volatile unsigned*)&g_state[bid] = (1u << 30) | (unsigned)block_total;
            int sum = 0;
            for (int p = bid - 1; p >= 0; ) {
                unsigned s;
                do { s = *(volatile unsigned*)&g_state[p]; } while ((s >> 30) == 0u);
                sum += (int)(s & 0x3FFFFFFFu);
                if ((s >> 30) == 2u) break;
                --p;
            }
            *(volatile unsigned*)&g_state[bid] = (2u << 30) | (unsigned)(sum + block_total);
            s_prev = sum;
        }
    }
    __syncthreads();
    if (i < N_NODES) {
        int off = excl + s_prev;
        g_off[i] = off;
        g_pos[i] = off;
    }
    if (bid == 0 && tid == 0) g_off[N_NODES] = N_EDGES;
}

// fill, 8 edges/thread (+ re-zero g_deg, g_state for next call)
__global__ void k_fill(const void* ei) {
    __shared__ int s_is32;
    int tid = threadIdx.x;
    int is32 = detect_is32(ei, tid, &s_is32);

    int base = blockIdx.x * 2048 + tid;
    int s[8], d[8];
    #pragma unroll
    for (int k = 0; k < 8; k++) {
        int e = base + k * 256;
        if (e < N_EDGES) {
            s[k] = load_idx(ei, e, is32);
            d[k] = load_idx(ei, (long long)N_EDGES + e, is32);
        } else d[k] = -1;
    }
    #pragma unroll
    for (int k = 0; k < 8; k++) {
        if (d[k] >= 0) {
            int p = atomicAdd(&g_pos[d[k]], 1);
            g_csr[p] = s[k];
        }
    }
    int gid = blockIdx.x * 256 + tid;
    if (gid < N_NODES) g_deg[gid] = 0;
    if (gid < 64) g_state[gid] = 0u;
}

// ---------------- layer-1 aggregation (F=16, f32) ----------------
// Full warp per node: lanes cover 2 neighbors x 16 features; unroll x4
// (8 neighbors in flight). Halves merged via shfl at the end.
__global__ void k_agg16(const float* __restrict__ x) {
    int warp = (blockIdx.x * blockDim.x + threadIdx.x) >> 5;
    int lane = threadIdx.x & 31;
    if (warp >= N_NODES) return;
    int half = lane >> 4;       // neighbor-pair slot
    int feat = lane & 15;
    int beg = g_off[warp], end = g_off[warp + 1];
    float acc = 0.f;
    int i = beg;
    for (; i + 8 <= end; i += 8) {
        float v[4];
        #pragma unroll
        for (int u = 0; u < 4; u++) {
            int s = g_csr[i + 2 * u + half];
            v[u] = x[(size_t)s * IN_DIM + feat];
        }
        acc += (v[0] + v[1]) + (v[2] + v[3]);
    }
    for (; i + 2 <= end; i += 2) {
        int s = g_csr[i + half];
        acc += x[(size_t)s * IN_DIM + feat];
    }
    if (i < end && half == 0) {
        int s = g_csr[i];
        acc += x[(size_t)s * IN_DIM + feat];
    }
    acc += __shfl_xor_sync(0xffffffffu, acc, 16);
    float inv = 1.0f / fmaxf((float)(end - beg), 1.0f);
    if (lane < 16) g_agg[(size_t)warp * IN_DIM + lane] = acc * inv;
}

// F=128 mean agg: 2 warps per node, each covers 64 features (half2 per lane).
// Reads ONLY the fp16 hi activations; writes fp16 hi/lo mean. Unroll x8.
__global__ void k_agg128(const f16* __restrict__ Hh,
                         f16* __restrict__ oh, f16* __restrict__ ol) {
    int gw = (blockIdx.x * blockDim.x + threadIdx.x) >> 5;
    int lane = threadIdx.x & 31;
    int node = gw >> 1;
    if (node >= N_NODES) return;
    int loff = ((gw & 1) << 6) + (lane << 1);   // feature offset (2 per lane)
    int beg = g_off[node], end = g_off[node + 1];
    float a0 = 0.f, a1 = 0.f;
    int i = beg;
    for (; i + 8 <= end; i += 8) {
        uint32_t u[8];
        #pragma unroll
        for (int k = 0; k < 8; k++) {
            int s = g_csr[i + k];
            u[k] = *(const uint32_t*)(Hh + ((size_t)s << 7) + loff);
        }
        #pragma unroll
        for (int k = 0; k < 8; k++) {
            float2 f = __half22float2(*(__half2*)&u[k]);
            a0 += f.x; a1 += f.y;
        }
    }
    for (; i + 4 <= end; i += 4) {
        uint32_t u[4];
        #pragma unroll
        for (int k = 0; k < 4; k++) {
            int s = g_csr[i + k];
            u[k] = *(const uint32_t*)(Hh + ((size_t)s << 7) + loff);
        }
        #pragma unroll
        for (int k = 0; k < 4; k++) {
            float2 f = __half22float2(*(__half2*)&u[k]);
            a0 += f.x; a1 += f.y;
        }
    }
    for (; i < end; i++) {
        int s = g_csr[i];
        uint32_t u = *(const uint32_t*)(Hh + ((size_t)s << 7) + loff);
        float2 f = __half22float2(*(__half2*)&u);
        a0 += f.x; a1 += f.y;
    }
    float inv = 1.0f / fmaxf((float)(end - beg), 1.0f);
    f16 vh[2], vl[2];
    hsplit(a0 * inv, vh[0], vl[0]);
    hsplit(a1 * inv, vh[1], vl[1]);
    size_t o = ((size_t)node << 7) + loff;
    *(uint32_t*)(oh + o) = *(const uint32_t*)vh;
    *(uint32_t*)(ol + o) = *(const uint32_t*)vl;
}

// ---------------- layer-1 FFMA GEMM (K=16 per segment), fp16 hi/lo out -----
__global__ __launch_bounds__(256)
void k_sage_gemm(const float* __restrict__ A1, const float* __restrict__ A2,
                 const float* __restrict__ W1, const float* __restrict__ W2,
                 const float* __restrict__ bias,
                 f16* __restrict__ out_hi, f16* __restrict__ out_lo,
                 int K)
{
    __shared__ float As[16][128];
    __shared__ float Ws[16][128];
    int tid = threadIdx.x;
    int tx = tid & 15;
    int ty = tid >> 4;
    int row0 = blockIdx.x * 128;

    float c[8][8];
    #pragma unroll
    for (int i = 0; i < 8; i++)
        #pragma unroll
        for (int j = 0; j < 8; j++) c[i][j] = 0.f;

    #pragma unroll
    for (int seg = 0; seg < 2; seg++) {
        const float* A = seg ? A2 : A1;
        const float* W = seg ? W2 : W1;
        for (int kk = 0; kk < K; kk += 16) {
            #pragma unroll
            for (int t = 0; t < 2; t++) {
                int idx = tid + t * 256;
                int m  = idx >> 2;
                int kq = idx & 3;
                int gm = row0 + m;
                float4 v = make_float4(0.f, 0.f, 0.f, 0.f);
                if (gm < N_NODES)
                    v = *(const float4*)(A + (size_t)gm * K + kk + kq * 4);
                As[kq * 4 + 0][m] = v.x; As[kq * 4 + 1][m] = v.y;
                As[kq * 4 + 2][m] = v.z; As[kq * 4 + 3][m] = v.w;
                float4 w = *(const float4*)(W + (size_t)m * K + kk + kq * 4);
                Ws[kq * 4 + 0][m] = w.x; Ws[kq * 4 + 1][m] = w.y;
                Ws[kq * 4 + 2][m] = w.z; Ws[kq * 4 + 3][m] = w.w;
            }
            __syncthreads();
            #pragma unroll
            for (int k = 0; k < 16; k++) {
                float a[8], w[8];
                *(float4*)&a[0] = *(const float4*)&As[k][ty * 8];
                *(float4*)&a[4] = *(const float4*)&As[k][ty * 8 + 4];
                *(float4*)&w[0] = *(const float4*)&Ws[k][tx * 8];
                *(float4*)&w[4] = *(const float4*)&Ws[k][tx * 8 + 4];
                #pragma unroll
                for (int i = 0; i < 8; i++)
                    #pragma unroll
                    for (int j = 0; j < 8; j++)
                        c[i][j] += a[i] * w[j];
            }
            __syncthreads();
        }
    }

    #pragma unroll
    for (int i = 0; i < 8; i++) {
        int gm = row0 + ty * 8 + i;
        if (gm >= N_NODES) continue;
        #pragma unroll
        for (int j = 0; j < 8; j += 4) {
            int gn = tx * 8 + j;
            f16 vh[4], vl[4];
            #pragma unroll
            for (int q = 0; q < 4; q++) {
                float v = fmaxf(c[i][j + q] + bias[gn + q], 0.f);
                hsplit(v, vh[q], vl[q]);
            }
            *(uint2*)(out_hi + (size_t)gm * 128 + gn) = *(const uint2*)vh;
            *(uint2*)(out_lo + (size_t)gm * 128 + gn) = *(const uint2*)vl;
        }
    }
}

// ---------------- fp16 split-HMMA GEMM, cp.async pipelined + ldmatrix -------
// out[M,128] = relu([A1|A2](M,256) @ [B1|B2](128,256)^T + bias)
// mode 0: write fp16 hi/lo activations.  mode 1: fused head -> outd[M,4].
#define TSTRIDE 80          // bytes per smem row
#define TILE_AL 10240
#define TILE_WH 20480
#define TILE_WL 30720
#define STAGE_B 40960

__global__ __launch_bounds__(256, 2)
void k_mma_gemm(const f16* __restrict__ A1h, const f16* __restrict__ A1l,
                const f16* __restrict__ A2h, const f16* __restrict__ A2l,
                const f16* __restrict__ B1h, const f16* __restrict__ B1l,
                const f16* __restrict__ B2h, const f16* __restrict__ B2l,
                const float* __restrict__ bias,
                f16* __restrict__ outh, f16* __restrict__ outl,
                const float* __restrict__ Whd, const float* __restrict__ bhd,
                float* __restrict__ outd,
                int mode)
{
    extern __shared__ char sm[];
    uint32_t smb = (uint32_t)__cvta_generic_to_shared(sm);

    int tid = threadIdx.x;
    int wid = tid >> 5;
    int lane = tid & 31;
    int warp_m = wid & 3;
    int warp_n = wid >> 2;
    int row0 = blockIdx.x * 128;

    int g = lane >> 3;
    uint32_t aoff = (uint32_t)(((lane & 7) + ((g & 1) << 3)) * TSTRIDE + (g >> 1) * 16);
    uint32_t boff = (uint32_t)((lane & 7) * TSTRIDE + ((lane >> 3) & 1) * 16);

    int lm = (tid >> 2);
    int lq = (tid & 3);
    uint32_t dof0 = (uint32_t)(lm * TSTRIDE + lq * 16);
    uint32_t dof1 = (uint32_t)((lm + 64) * TSTRIDE + lq * 16);

    float c[2][8][4];
    #pragma unroll
    for (int mt = 0; mt < 2; mt++)
        #pragma unroll
        for (int nt = 0; nt < 8; nt++)
            #pragma unroll
            for (int q = 0; q < 4; q++) c[mt][nt][q] = 0.f;

    auto load_chunk = [&](int ch, int stage) {
        int seg = ch >> 2;
        int k0 = (ch & 3) * 32;
        const f16* Ah = seg ? A2h : A1h;
        const f16* Al = seg ? A2l : A1l;
        const f16* Bh = seg ? B2h : B1h;
        const f16* Bl = seg ? B2l : B1l;
        uint32_t SB = smb + stage * STAGE_B;
        #pragma unroll
        for (int t = 0; t < 2; t++) {
            int m = (t == 0) ? lm : lm + 64;
            uint32_t dof = (t == 0) ? dof0 : dof1;
            int gm = row0 + m;
            uint32_t sz = (gm < N_NODES) ? 16u : 0u;
            size_t gmc = (gm < N_NODES) ? (size_t)gm : 0;
            CP16(SB + dof,           Ah + (gmc << 7) + k0 + lq * 8, sz);
            CP16(SB + TILE_AL + dof, Al + (gmc << 7) + k0 + lq * 8, sz);
            CP16(SB + TILE_WH + dof, Bh + ((size_t)m << 7) + k0 + lq * 8, 16u);
            CP16(SB + TILE_WL + dof, Bl + ((size_t)m << 7) + k0 + lq * 8, 16u);
        }
    };

    load_chunk(0, 0);
    CP_COMMIT();

    for (int ch = 0; ch < 8; ch++) {
        if (ch < 7) {
            load_chunk(ch + 1, (ch + 1) & 1);
            CP_COMMIT();
            CP_WAIT1();
        } else {
            CP_WAIT0();
        }
        __syncthreads();

        uint32_t SB = smb + (ch & 1) * STAGE_B;
        #pragma unroll
        for (int ks = 0; ks < 2; ks++) {
            uint32_t kso = (uint32_t)(ks * 32);
            uint32_t ah[2][4], al[2][4];
            #pragma unroll
            for (int mt = 0; mt < 2; mt++) {
                uint32_t abase = SB + (uint32_t)((warp_m * 32 + mt * 16) * TSTRIDE) + kso + aoff;
                LDSM4(ah[mt], abase);
                LDSM4(al[mt], abase + TILE_AL);
            }
            #pragma unroll
            for (int nt = 0; nt < 8; nt++) {
                uint32_t bbase = SB + TILE_WH + (uint32_t)((warp_n * 64 + nt * 8) * TSTRIDE) + kso + boff;
                uint32_t bh0, bh1, bl0, bl1;
                LDSM2(bh0, bh1, bbase);
                LDSM2(bl0, bl1, bbase + (TILE_WL - TILE_WH));
                #pragma unroll
                for (int mt = 0; mt < 2; mt++) {
                    mma_f16(c[mt][nt], ah[mt], bh0, bh1);
                    mma_f16(c[mt][nt], ah[mt], bl0, bl1);
                    mma_f16(c[mt][nt], al[mt], bh0, bh1);
                }
            }
        }
        __syncthreads();
    }

    int tg = lane & 3;
    int gp = lane >> 2;

    if (mode == 0) {
        #pragma unroll
        for (int mt = 0; mt < 2; mt++) {
            int row = row0 + warp_m * 32 + mt * 16 + gp;
            #pragma unroll
            for (int nt = 0; nt < 8; nt++) {
                int col = warp_n * 64 + nt * 8 + 2 * tg;
                float b0 = bias[col], b1 = bias[col + 1];
                #pragma unroll
                for (int half = 0; half < 2; half++) {
                    int r = row + half * 8;
                    if (r < N_NODES) {
                        float v0 = fmaxf(c[mt][nt][half * 2 + 0] + b0, 0.f);
                        float v1 = fmaxf(c[mt][nt][half * 2 + 1] + b1, 0.f);
                        f16 h0, l0, h1, l1;
                        hsplit(v0, h0, l0); hsplit(v1, h1, l1);
                        f16 hh[2] = {h0, h1}, ll[2] = {l0, l1};
                        *(uint32_t*)(outh + (size_t)r * 128 + col) = *(const uint32_t*)hh;
                        *(uint32_t*)(outl + (size_t)r * 128 + col) = *(const uint32_t*)ll;
                    }
                }
            }
        }
    } else {
        // fused head: out[r, 0..3] = relu(h3[r,:]) @ Wh^T + bh
        float p[4][4];
        #pragma unroll
        for (int i = 0; i < 4; i++)
            #pragma unroll
            for (int o = 0; o < 4; o++) p[i][o] = 0.f;

        #pragma unroll
        for (int mt = 0; mt < 2; mt++) {
            #pragma unroll
            for (int nt = 0; nt < 8; nt++) {
                int col = warp_n * 64 + nt * 8 + 2 * tg;
                float b0 = bias[col], b1 = bias[col + 1];
                #pragma unroll
                for (int half = 0; half < 2; half++) {
                    float v0 = fmaxf(c[mt][nt][half * 2 + 0] + b0, 0.f);
                    float v1 = fmaxf(c[mt][nt][half * 2 + 1] + b1, 0.f);
                    #pragma unroll
                    for (int o = 0; o < 4; o++) {
                        p[mt * 2 + half][o] += v0 * Whd[o * 128 + col]
                                             + v1 * Whd[o * 128 + col + 1];
                    }
                }
            }
        }
        #pragma unroll
        for (int i = 0; i < 4; i++)
            #pragma unroll
            for (int o = 0; o < 4; o++) {
                float v = p[i][o];
                v += __shfl_xor_sync(0xffffffffu, v, 1);
                v += __shfl_xor_sync(0xffffffffu, v, 2);
                p[i][o] = v;
            }
        float* sred = (float*)sm;   // [128][8]
        if (tg == 0) {
            #pragma unroll
            for (int mt = 0; mt < 2; mt++)
                #pragma unroll
                for (int half = 0; half < 2; half++) {
                    int rl = warp_m * 32 + mt * 16 + half * 8 + gp;
                    #pragma unroll
                    for (int o = 0; o < 4; o++)
                        sred[rl * 8 + warp_n * 4 + o] = p[mt * 2 + half][o];
                }
        }
        __syncthreads();
        for (int t = tid; t < 512; t += 256) {
            int rl = t >> 2, o = t & 3;
            int r = row0 + rl;
            if (r < N_NODES)
                outd[(size_t)r * 4 + o] = sred[rl * 8 + o] + sred[rl * 8 + 4 + o] + bhd[o];
        }
    }
}

// ---------------- launch ----------------
extern "C" void kernel_launch(void* const* d_in, const int* in_sizes, int n_in,
                              void* d_out, int out_size)
{
    const float* x   = (const float*)d_in[0];
    const void*  ei  = d_in[1];
    const float* Wl1 = (const float*)d_in[2];
    const float* Wr1 = (const float*)d_in[3];
    const float* b1  = (const float*)d_in[4];
    const float* Wl2 = (const float*)d_in[5];
    const float* Wr2 = (const float*)d_in[6];
    const float* b2  = (const float*)d_in[7];
    const float* Wl3 = (const float*)d_in[8];
    const float* Wr3 = (const float*)d_in[9];
    const float* b3  = (const float*)d_in[10];
    const float* Wh  = (const float*)d_in[11];
    const float* bh  = (const float*)d_in[12];
    float* out = (float*)d_out;

    float *p_agg;
    f16 *p_aggh, *p_aggl, *p_h1h, *p_h1l, *p_h2h, *p_h2l, *p_Whs, *p_Wls;
    cudaGetSymbolAddress((void**)&p_agg,  g_agg);
    cudaGetSymbolAddress((void**)&p_aggh, g_aggh);
    cudaGetSymbolAddress((void**)&p_aggl, g_aggl);
    cudaGetSymbolAddress((void**)&p_h1h,  g_h1h);
    cudaGetSymbolAddress((void**)&p_h1l,  g_h1l);
    cudaGetSymbolAddress((void**)&p_h2h,  g_h2h);
    cudaGetSymbolAddress((void**)&p_h2l,  g_h2l);
    cudaGetSymbolAddress((void**)&p_Whs,  g_Wh);
    cudaGetSymbolAddress((void**)&p_Wls,  g_Wl);

    const int WB  = (N_NODES + 7) / 8;             // warp-per-node, 256 thr
    const int WB2 = (2 * N_NODES + 7) / 8;         // 2 warps per node
    const int GB  = (N_NODES + 127) / 128;         // 391
    const int SB  = (N_NODES + 1023) / 1024;       // 49
    const int CB8 = (N_EDGES + 2047) / 2048;       // 293
    const int MSM = 2 * STAGE_B;                   // 81920

    cudaFuncSetAttribute(k_mma_gemm, cudaFuncAttributeMaxDynamicSharedMemorySize, MSM);

    // graph structure (+ W split inside k_count; g_deg/g_state zero invariant)
    k_count<<<CB8, 256>>>(ei, Wl2, Wr2, Wl3, Wr3);
    k_scan<<<SB, 1024>>>();
    k_fill<<<CB8, 256>>>(ei);

    const int HH = HIDDEN * HIDDEN;

    // layer 1 (FFMA, K=16) -> h1 hi/lo
    k_agg16<<<WB, 256>>>(x);
    k_sage_gemm<<<GB, 256>>>(p_agg, x, Wl1, Wr1, b1, p_h1h, p_h1l, IN_DIM);

    // layer 2 (fp16 split HMMA, pipelined) -> h2 hi/lo
    k_agg128<<<WB2, 256>>>(p_h1h, p_aggh, p_aggl);
    k_mma_gemm<<<GB, 256, MSM>>>(p_aggh, p_aggl, p_h1h, p_h1l,
                                 p_Whs + 0 * HH, p_Wls + 0 * HH,
                                 p_Whs + 1 * HH, p_Wls + 1 * HH,
                                 b2, p_h2h, p_h2l, nullptr, nullptr, nullptr, 0);

    // layer 3 (fp16 split HMMA, pipelined) + fused head -> out
    k_agg128<<<WB2, 256>>>(p_h2h, p_aggh, p_aggl);
    k_mma_gemm<<<GB, 256, MSM>>>(p_aggh, p_aggl, p_h2h, p_h2l,
                                 p_Whs + 2 * HH, p_Wls + 2 * HH,
                                 p_Whs + 3 * HH, p_Wls + 3 * HH,
                                 b3, nullptr, nullptr, Wh, bh, out, 1);
}

// round 12
// speedup vs baseline: 1.1212x; 1.1212x over previous
#include <cuda_runtime.h>
#include <cuda_fp16.h>
#include <cstdint>
#include <cstddef>

#define N_NODES 50000
#define N_EDGES 600000
#define IN_DIM  16
#define HIDDEN  128
#define OUT_DIM 4

typedef __half f16;

// ---------------- device scratch (static: no allocs allowed) ----------------
// Invariants at entry to every kernel_launch call (zero-init at module load;
// re-zeroed in k_fill after consumption): g_deg == 0, g_state == 0.
__device__ int      g_deg[N_NODES];
__device__ unsigned g_state[64];
__device__ int      g_off[N_NODES + 1];
__device__ int      g_pos[N_NODES];
__device__ int      g_csr[N_EDGES];

__device__ float g_agg[(size_t)N_NODES * IN_DIM];      // layer1 agg (f32)
// fp16 hi/lo splits
__device__ f16   g_aggh[(size_t)N_NODES * HIDDEN];
__device__ f16   g_aggl[(size_t)N_NODES * HIDDEN];
__device__ f16   g_h1h[(size_t)N_NODES * HIDDEN];
__device__ f16   g_h1l[(size_t)N_NODES * HIDDEN];
__device__ f16   g_h2h[(size_t)N_NODES * HIDDEN];
__device__ f16   g_h2l[(size_t)N_NODES * HIDDEN];
// W splits: order Wl2, Wr2, Wl3, Wr3
__device__ f16   g_Wh[4][HIDDEN * HIDDEN];
__device__ f16   g_Wl[4][HIDDEN * HIDDEN];

// ---------------- helpers ----------------
__device__ __forceinline__ void hsplit(float x, f16& h, f16& l) {
    h = __float2half_rn(x);
    l = __float2half_rn(x - __half2float(h));
}

__device__ __forceinline__ void mma_f16(float c[4], const uint32_t a[4],
                                        uint32_t b0, uint32_t b1) {
    asm volatile(
        "mma.sync.aligned.m16n8k16.row.col.f32.f16.f16.f32 "
        "{%0,%1,%2,%3}, {%4,%5,%6,%7}, {%8,%9}, {%0,%1,%2,%3};"
        : "+f"(c[0]), "+f"(c[1]), "+f"(c[2]), "+f"(c[3])
        : "r"(a[0]), "r"(a[1]), "r"(a[2]), "r"(a[3]), "r"(b0), "r"(b1));
}

#define LDSM4(r, addr) \
    asm volatile("ldmatrix.sync.aligned.m8n8.x4.shared.b16 {%0,%1,%2,%3}, [%4];" \
        : "=r"((r)[0]), "=r"((r)[1]), "=r"((r)[2]), "=r"((r)[3]) : "r"(addr))
#define LDSM2(r0, r1, addr) \
    asm volatile("ldmatrix.sync.aligned.m8n8.x2.shared.b16 {%0,%1}, [%2];" \
        : "=r"(r0), "=r"(r1) : "r"(addr))
#define CP16(dst, src, sz) \
    asm volatile("cp.async.ca.shared.global [%0], [%1], 16, %2;" \
        :: "r"(dst), "l"(src), "r"(sz))
#define CP_COMMIT() asm volatile("cp.async.commit_group;")
#define CP_WAIT1()  asm volatile("cp.async.wait_group 1;")
#define CP_WAIT0()  asm volatile("cp.async.wait_group 0;")

__device__ __forceinline__ int load_idx(const void* ei, long long pos, int is32) {
    if (is32) return ((const int*)ei)[pos];
    return (int)(((const long long*)ei)[pos]);
}

// Block-local dtype detect: warp 0 scans 64 int64 slots; int32 data misread
// as int64 yields values outside [0, N_NODES) with overwhelming probability.
__device__ __forceinline__ int detect_is32(const void* ei, int tid, int* s_is32) {
    if (tid < 32) {
        const long long* p = (const long long*)ei;
        long long v0 = p[tid];
        long long v1 = p[32 + tid];
        int bad = (v0 < 0 || v0 >= N_NODES || v1 < 0 || v1 >= N_NODES) ? 1 : 0;
        unsigned m = __ballot_sync(0xffffffffu, bad);
        if (tid == 0) *s_is32 = m ? 1 : 0;
    }
    __syncthreads();
    return *s_is32;
}

// ---------------- CSR: count (+ W split folded in), 8 edges/thread ---------
__global__ void k_count(const void* ei,
                        const float* __restrict__ Wl2, const float* __restrict__ Wr2,
                        const float* __restrict__ Wl3, const float* __restrict__ Wr3) {
    __shared__ int s_is32;
    int tid = threadIdx.x;
    int is32 = detect_is32(ei, tid, &s_is32);

    // W split: first 65536 global threads handle one element each
    int gid = blockIdx.x * 256 + tid;
    if (gid < 65536) {
        int w = gid >> 14;
        int e = gid & 16383;
        const float* src = (w == 0) ? Wl2 : (w == 1) ? Wr2 : (w == 2) ? Wl3 : Wr3;
        float v = src[e];
        f16 h, l;
        hsplit(v, h, l);
        g_Wh[w][e] = h;
        g_Wl[w][e] = l;
    }

    int base = blockIdx.x * 2048 + tid;
    int d[8];
    #pragma unroll
    for (int k = 0; k < 8; k++) {
        int e = base + k * 256;
        d[k] = (e < N_EDGES) ? load_idx(ei, (long long)N_EDGES + e, is32) : -1;
    }
    #pragma unroll
    for (int k = 0; k < 8; k++)
        if (d[k] >= 0) atomicAdd(&g_deg[d[k]], 1);
}

// ---------------- single-pass scan with decoupled lookback ----------------
__global__ void k_scan() {
    __shared__ int warp_sums[32];
    __shared__ int s_prev;
    int tid = threadIdx.x;  // 1024
    int bid = blockIdx.x;
    int i = bid * 1024 + tid;
    int v = (i < N_NODES) ? g_deg[i] : 0;
    int x = v;
    #pragma unroll
    for (int d = 1; d < 32; d <<= 1) {
        int y = __shfl_up_sync(0xffffffffu, x, d);
        if ((tid & 31) >= d) x += y;
    }
    if ((tid & 31) == 31) warp_sums[tid >> 5] = x;
    __syncthreads();
    if (tid < 32) {
        int w = warp_sums[tid];
        #pragma unroll
        for (int d = 1; d < 32; d <<= 1) {
            int y = __shfl_up_sync(0xffffffffu, w, d);
            if (tid >= d) w += y;
        }
        warp_sums[tid] = w;
    }
    __syncthreads();
    int excl = x - v + ((tid >= 32) ? warp_sums[(tid >> 5) - 1] : 0);
    int block_total = warp_sums[31];

    if (tid == 0) {
        if (bid == 0) {
            *(volatile unsigned*)&g_state[0] = (2u << 30) | (unsigned)block_total;
            s_prev = 0;
        } else {
            *(volatile unsigned*)&g_state[bid] = (1u << 30) | (unsigned)block_total;
            int sum = 0;
            for (int p = bid - 1; p >= 0; ) {
                unsigned s;
                do { s = *(volatile unsigned*)&g_state[p]; } while ((s >> 30) == 0u);
                sum += (int)(s & 0x3FFFFFFFu);
                if ((s >> 30) == 2u) break;
                --p;
            }
            *(volatile unsigned*)&g_state[bid] = (2u << 30) | (unsigned)(sum + block_total);
            s_prev = sum;
        }
    }
    __syncthreads();
    if (i < N_NODES) {
        int off = excl + s_prev;
        g_off[i] = off;
        g_pos[i] = off;
    }
    if (bid == 0 && tid == 0) g_off[N_NODES] = N_EDGES;
}

// fill, 8 edges/thread (+ re-zero g_deg, g_state for next call)
__global__ void k_fill(const void* ei) {
    __shared__ int s_is32;
    int tid = threadIdx.x;
    int is32 = detect_is32(ei, tid, &s_is32);

    int base = blockIdx.x * 2048 + tid;
    int s[8], d[8];
    #pragma unroll
    for (int k = 0; k < 8; k++) {
        int e = base + k * 256;
        if (e < N_EDGES) {
            s[k] = load_idx(ei, e, is32);
            d[k] = load_idx(ei, (long long)N_EDGES + e, is32);
        } else d[k] = -1;
    }
    #pragma unroll
    for (int k = 0; k < 8; k++) {
        if (d[k] >= 0) {
            int p = atomicAdd(&g_pos[d[k]], 1);
            g_csr[p] = s[k];
        }
    }
    int gid = blockIdx.x * 256 + tid;
    if (gid < N_NODES) g_deg[gid] = 0;
    if (gid < 64) g_state[gid] = 0u;
}

// ---------------- layer-1 aggregation (F=16, f32) ----------------
// Full warp per node: lanes cover 2 neighbors x 16 features; unroll x4
// (8 neighbors in flight). Halves merged via shfl at the end.
__global__ void k_agg16(const float* __restrict__ x) {
    int warp = (blockIdx.x * blockDim.x + threadIdx.x) >> 5;
    int lane = threadIdx.x & 31;
    if (warp >= N_NODES) return;
    int half = lane >> 4;       // neighbor-pair slot
    int feat = lane & 15;
    int beg = g_off[warp], end = g_off[warp + 1];
    float acc = 0.f;
    int i = beg;
    for (; i + 8 <= end; i += 8) {
        float v[4];
        #pragma unroll
        for (int u = 0; u < 4; u++) {
            int s = g_csr[i + 2 * u + half];
            v[u] = x[(size_t)s * IN_DIM + feat];
        }
        acc += (v[0] + v[1]) + (v[2] + v[3]);
    }
    for (; i + 2 <= end; i += 2) {
        int s = g_csr[i + half];
        acc += x[(size_t)s * IN_DIM + feat];
    }
    if (i < end && half == 0) {
        int s = g_csr[i];
        acc += x[(size_t)s * IN_DIM + feat];
    }
    acc += __shfl_xor_sync(0xffffffffu, acc, 16);
    float inv = 1.0f / fmaxf((float)(end - beg), 1.0f);
    if (lane < 16) g_agg[(size_t)warp * IN_DIM + lane] = acc * inv;
}

// F=128 mean agg: 1 warp per node, reads ONLY fp16 hi activations (uint2 per
// lane, 256B/row), f32 acc, writes fp16 hi/lo mean. Unroll x8 / x4 / x1.
__global__ void k_agg128(const f16* __restrict__ Hh,
                         f16* __restrict__ oh, f16* __restrict__ ol) {
    int warp = (blockIdx.x * blockDim.x + threadIdx.x) >> 5;
    int lane = threadIdx.x & 31;
    if (warp >= N_NODES) return;
    int beg = g_off[warp], end = g_off[warp + 1];
    float a0 = 0.f, a1 = 0.f, a2 = 0.f, a3 = 0.f;
    int loff = lane << 2;
    int i = beg;
    for (; i + 8 <= end; i += 8) {
        uint2 u[8];
        #pragma unroll
        for (int k = 0; k < 8; k++) {
            int s = g_csr[i + k];
            u[k] = *(const uint2*)(Hh + ((size_t)s << 7) + loff);
        }
        #pragma unroll
        for (int k = 0; k < 8; k++) {
            float2 f;
            f = __half22float2(*(__half2*)&u[k].x); a0 += f.x; a1 += f.y;
            f = __half22float2(*(__half2*)&u[k].y); a2 += f.x; a3 += f.y;
        }
    }
    for (; i + 4 <= end; i += 4) {
        uint2 u[4];
        #pragma unroll
        for (int k = 0; k < 4; k++) {
            int s = g_csr[i + k];
            u[k] = *(const uint2*)(Hh + ((size_t)s << 7) + loff);
        }
        #pragma unroll
        for (int k = 0; k < 4; k++) {
            float2 f;
            f = __half22float2(*(__half2*)&u[k].x); a0 += f.x; a1 += f.y;
            f = __half22float2(*(__half2*)&u[k].y); a2 += f.x; a3 += f.y;
        }
    }
    for (; i < end; i++) {
        int s = g_csr[i];
        uint2 u = *(const uint2*)(Hh + ((size_t)s << 7) + loff);
        float2 f;
        f = __half22float2(*(__half2*)&u.x); a0 += f.x; a1 += f.y;
        f = __half22float2(*(__half2*)&u.y); a2 += f.x; a3 += f.y;
    }
    float inv = 1.0f / fmaxf((float)(end - beg), 1.0f);
    f16 vh[4], vl[4];
    hsplit(a0 * inv, vh[0], vl[0]);
    hsplit(a1 * inv, vh[1], vl[1]);
    hsplit(a2 * inv, vh[2], vl[2]);
    hsplit(a3 * inv, vh[3], vl[3]);
    size_t o = ((size_t)warp << 7) + loff;
    *(uint2*)(oh + o) = *(const uint2*)vh;
    *(uint2*)(ol + o) = *(const uint2*)vl;
}

// ---------------- layer-1 FFMA GEMM (K=16 per segment), fp16 hi/lo out -----
__global__ __launch_bounds__(256)
void k_sage_gemm(const float* __restrict__ A1, const float* __restrict__ A2,
                 const float* __restrict__ W1, const float* __restrict__ W2,
                 const float* __restrict__ bias,
                 f16* __restrict__ out_hi, f16* __restrict__ out_lo,
                 int K)
{
    __shared__ float As[16][128];
    __shared__ float Ws[16][128];
    int tid = threadIdx.x;
    int tx = tid & 15;
    int ty = tid >> 4;
    int row0 = blockIdx.x * 128;

    float c[8][8];
    #pragma unroll
    for (int i = 0; i < 8; i++)
        #pragma unroll
        for (int j = 0; j < 8; j++) c[i][j] = 0.f;

    #pragma unroll
    for (int seg = 0; seg < 2; seg++) {
        const float* A = seg ? A2 : A1;
        const float* W = seg ? W2 : W1;
        for (int kk = 0; kk < K; kk += 16) {
            #pragma unroll
            for (int t = 0; t < 2; t++) {
                int idx = tid + t * 256;
                int m  = idx >> 2;
                int kq = idx & 3;
                int gm = row0 + m;
                float4 v = make_float4(0.f, 0.f, 0.f, 0.f);
                if (gm < N_NODES)
                    v = *(const float4*)(A + (size_t)gm * K + kk + kq * 4);
                As[kq * 4 + 0][m] = v.x; As[kq * 4 + 1][m] = v.y;
                As[kq * 4 + 2][m] = v.z; As[kq * 4 + 3][m] = v.w;
                float4 w = *(const float4*)(W + (size_t)m * K + kk + kq * 4);
                Ws[kq * 4 + 0][m] = w.x; Ws[kq * 4 + 1][m] = w.y;
                Ws[kq * 4 + 2][m] = w.z; Ws[kq * 4 + 3][m] = w.w;
            }
            __syncthreads();
            #pragma unroll
            for (int k = 0; k < 16; k++) {
                float a[8], w[8];
                *(float4*)&a[0] = *(const float4*)&As[k][ty * 8];
                *(float4*)&a[4] = *(const float4*)&As[k][ty * 8 + 4];
                *(float4*)&w[0] = *(const float4*)&Ws[k][tx * 8];
                *(float4*)&w[4] = *(const float4*)&Ws[k][tx * 8 + 4];
                #pragma unroll
                for (int i = 0; i < 8; i++)
                    #pragma unroll
                    for (int j = 0; j < 8; j++)
                        c[i][j] += a[i] * w[j];
            }
            __syncthreads();
        }
    }

    #pragma unroll
    for (int i = 0; i < 8; i++) {
        int gm = row0 + ty * 8 + i;
        if (gm >= N_NODES) continue;
        #pragma unroll
        for (int j = 0; j < 8; j += 4) {
            int gn = tx * 8 + j;
            f16 vh[4], vl[4];
            #pragma unroll
            for (int q = 0; q < 4; q++) {
                float v = fmaxf(c[i][j + q] + bias[gn + q], 0.f);
                hsplit(v, vh[q], vl[q]);
            }
            *(uint2*)(out_hi + (size_t)gm * 128 + gn) = *(const uint2*)vh;
            *(uint2*)(out_lo + (size_t)gm * 128 + gn) = *(const uint2*)vl;
        }
    }
}

// ---------------- fp16 split-HMMA GEMM, cp.async pipelined + ldmatrix -------
// out[M,128] = relu([A1|A2](M,256) @ [B1|B2](128,256)^T + bias)
// mode 0: write fp16 hi/lo activations.  mode 1: fused head -> outd[M,4].
#define TSTRIDE 80          // bytes per smem row
#define TILE_AL 10240
#define TILE_WH 20480
#define TILE_WL 30720
#define STAGE_B 40960

__global__ __launch_bounds__(256, 2)
void k_mma_gemm(const f16* __restrict__ A1h, const f16* __restrict__ A1l,
                const f16* __restrict__ A2h, const f16* __restrict__ A2l,
                const f16* __restrict__ B1h, const f16* __restrict__ B1l,
                const f16* __restrict__ B2h, const f16* __restrict__ B2l,
                const float* __restrict__ bias,
                f16* __restrict__ outh, f16* __restrict__ outl,
                const float* __restrict__ Whd, const float* __restrict__ bhd,
                float* __restrict__ outd,
                int mode)
{
    extern __shared__ char sm[];
    uint32_t smb = (uint32_t)__cvta_generic_to_shared(sm);

    int tid = threadIdx.x;
    int wid = tid >> 5;
    int lane = tid & 31;
    int warp_m = wid & 3;
    int warp_n = wid >> 2;
    int row0 = blockIdx.x * 128;

    int g = lane >> 3;
    uint32_t aoff = (uint32_t)(((lane & 7) + ((g & 1) << 3)) * TSTRIDE + (g >> 1) * 16);
    uint32_t boff = (uint32_t)((lane & 7) * TSTRIDE + ((lane >> 3) & 1) * 16);

    int lm = (tid >> 2);
    int lq = (tid & 3);
    uint32_t dof0 = (uint32_t)(lm * TSTRIDE + lq * 16);
    uint32_t dof1 = (uint32_t)((lm + 64) * TSTRIDE + lq * 16);

    float c[2][8][4];
    #pragma unroll
    for (int mt = 0; mt < 2; mt++)
        #pragma unroll
        for (int nt = 0; nt < 8; nt++)
            #pragma unroll
            for (int q = 0; q < 4; q++) c[mt][nt][q] = 0.f;

    auto load_chunk = [&](int ch, int stage) {
        int seg = ch >> 2;
        int k0 = (ch & 3) * 32;
        const f16* Ah = seg ? A2h : A1h;
        const f16* Al = seg ? A2l : A1l;
        const f16* Bh = seg ? B2h : B1h;
        const f16* Bl = seg ? B2l : B1l;
        uint32_t SB = smb + stage * STAGE_B;
        #pragma unroll
        for (int t = 0; t < 2; t++) {
            int m = (t == 0) ? lm : lm + 64;
            uint32_t dof = (t == 0) ? dof0 : dof1;
            int gm = row0 + m;
            uint32_t sz = (gm < N_NODES) ? 16u : 0u;
            size_t gmc = (gm < N_NODES) ? (size_t)gm : 0;
            CP16(SB + dof,           Ah + (gmc << 7) + k0 + lq * 8, sz);
            CP16(SB + TILE_AL + dof, Al + (gmc << 7) + k0 + lq * 8, sz);
            CP16(SB + TILE_WH + dof, Bh + ((size_t)m << 7) + k0 + lq * 8, 16u);
            CP16(SB + TILE_WL + dof, Bl + ((size_t)m << 7) + k0 + lq * 8, 16u);
        }
    };

    load_chunk(0, 0);
    CP_COMMIT();

    for (int ch = 0; ch < 8; ch++) {
        if (ch < 7) {
            load_chunk(ch + 1, (ch + 1) & 1);
            CP_COMMIT();
            CP_WAIT1();
        } else {
            CP_WAIT0();
        }
        __syncthreads();

        uint32_t SB = smb + (ch & 1) * STAGE_B;
        #pragma unroll
        for (int ks = 0; ks < 2; ks++) {
            uint32_t kso = (uint32_t)(ks * 32);
            uint32_t ah[2][4], al[2][4];
            #pragma unroll
            for (int mt = 0; mt < 2; mt++) {
                uint32_t abase = SB + (uint32_t)((warp_m * 32 + mt * 16) * TSTRIDE) + kso + aoff;
                LDSM4(ah[mt], abase);
                LDSM4(al[mt], abase + TILE_AL);
            }
            #pragma unroll
            for (int nt = 0; nt < 8; nt++) {
                uint32_t bbase = SB + TILE_WH + (uint32_t)((warp_n * 64 + nt * 8) * TSTRIDE) + kso + boff;
                uint32_t bh0, bh1, bl0, bl1;
                LDSM2(bh0, bh1, bbase);
                LDSM2(bl0, bl1, bbase + (TILE_WL - TILE_WH));
                #pragma unroll
                for (int mt = 0; mt < 2; mt++) {
                    mma_f16(c[mt][nt], ah[mt], bh0, bh1);
                    mma_f16(c[mt][nt], ah[mt], bl0, bl1);
                    mma_f16(c[mt][nt], al[mt], bh0, bh1);
                }
            }
        }
        __syncthreads();
    }

    int tg = lane & 3;
    int gp = lane >> 2;

    if (mode == 0) {
        #pragma unroll
        for (int mt = 0; mt < 2; mt++) {
            int row = row0 + warp_m * 32 + mt * 16 + gp;
            #pragma unroll
            for (int nt = 0; nt < 8; nt++) {
                int col = warp_n * 64 + nt * 8 + 2 * tg;
                float b0 = bias[col], b1 = bias[col + 1];
                #pragma unroll
                for (int half = 0; half < 2; half++) {
                    int r = row + half * 8;
                    if (r < N_NODES) {
                        float v0 = fmaxf(c[mt][nt][half * 2 + 0] + b0, 0.f);
                        float v1 = fmaxf(c[mt][nt][half * 2 + 1] + b1, 0.f);
                        f16 h0, l0, h1, l1;
                        hsplit(v0, h0, l0); hsplit(v1, h1, l1);
                        f16 hh[2] = {h0, h1}, ll[2] = {l0, l1};
                        *(uint32_t*)(outh + (size_t)r * 128 + col) = *(const uint32_t*)hh;
                        *(uint32_t*)(outl + (size_t)r * 128 + col) = *(const uint32_t*)ll;
                    }
                }
            }
        }
    } else {
        // fused head: out[r, 0..3] = relu(h3[r,:]) @ Wh^T + bh
        float p[4][4];
        #pragma unroll
        for (int i = 0; i < 4; i++)
            #pragma unroll
            for (int o = 0; o < 4; o++) p[i][o] = 0.f;

        #pragma unroll
        for (int mt = 0; mt < 2; mt++) {
            #pragma unroll
            for (int nt = 0; nt < 8; nt++) {
                int col = warp_n * 64 + nt * 8 + 2 * tg;
                float b0 = bias[col], b1 = bias[col + 1];
                #pragma unroll
                for (int half = 0; half < 2; half++) {
                    float v0 = fmaxf(c[mt][nt][half * 2 + 0] + b0, 0.f);
                    float v1 = fmaxf(c[mt][nt][half * 2 + 1] + b1, 0.f);
                    #pragma unroll
                    for (int o = 0; o < 4; o++) {
                        p[mt * 2 + half][o] += v0 * Whd[o * 128 + col]
                                             + v1 * Whd[o * 128 + col + 1];
                    }
                }
            }
        }
        #pragma unroll
        for (int i = 0; i < 4; i++)
            #pragma unroll
            for (int o = 0; o < 4; o++) {
                float v = p[i][o];
                v += __shfl_xor_sync(0xffffffffu, v, 1);
                v += __shfl_xor_sync(0xffffffffu, v, 2);
                p[i][o] = v;
            }
        float* sred = (float*)sm;   // [128][8]
        if (tg == 0) {
            #pragma unroll
            for (int mt = 0; mt < 2; mt++)
                #pragma unroll
                for (int half = 0; half < 2; half++) {
                    int rl = warp_m * 32 + mt * 16 + half * 8 + gp;
                    #pragma unroll
                    for (int o = 0; o < 4; o++)
                        sred[rl * 8 + warp_n * 4 + o] = p[mt * 2 + half][o];
                }
        }
        __syncthreads();
        for (int t = tid; t < 512; t += 256) {
            int rl = t >> 2, o = t & 3;
            int r = row0 + rl;
            if (r < N_NODES)
                outd[(size_t)r * 4 + o] = sred[rl * 8 + o] + sred[rl * 8 + 4 + o] + bhd[o];
        }
    }
}

// ---------------- launch ----------------
extern "C" void kernel_launch(void* const* d_in, const int* in_sizes, int n_in,
                              void* d_out, int out_size)
{
    const float* x   = (const float*)d_in[0];
    const void*  ei  = d_in[1];
    const float* Wl1 = (const float*)d_in[2];
    const float* Wr1 = (const float*)d_in[3];
    const float* b1  = (const float*)d_in[4];
    const float* Wl2 = (const float*)d_in[5];
    const float* Wr2 = (const float*)d_in[6];
    const float* b2  = (const float*)d_in[7];
    const float* Wl3 = (const float*)d_in[8];
    const float* Wr3 = (const float*)d_in[9];
    const float* b3  = (const float*)d_in[10];
    const float* Wh  = (const float*)d_in[11];
    const float* bh  = (const float*)d_in[12];
    float* out = (float*)d_out;

    float *p_agg;
    f16 *p_aggh, *p_aggl, *p_h1h, *p_h1l, *p_h2h, *p_h2l, *p_Whs, *p_Wls;
    cudaGetSymbolAddress((void**)&p_agg,  g_agg);
    cudaGetSymbolAddress((void**)&p_aggh, g_aggh);
    cudaGetSymbolAddress((void**)&p_aggl, g_aggl);
    cudaGetSymbolAddress((void**)&p_h1h,  g_h1h);
    cudaGetSymbolAddress((void**)&p_h1l,  g_h1l);
    cudaGetSymbolAddress((void**)&p_h2h,  g_h2h);
    cudaGetSymbolAddress((void**)&p_h2l,  g_h2l);
    cudaGetSymbolAddress((void**)&p_Whs,  g_Wh);
    cudaGetSymbolAddress((void**)&p_Wls,  g_Wl);

    const int WB  = (N_NODES + 7) / 8;             // warp-per-node, 256 thr
    const int GB  = (N_NODES + 127) / 128;         // 391
    const int SB  = (N_NODES + 1023) / 1024;       // 49
    const int CB8 = (N_EDGES + 2047) / 2048;       // 293
    const int MSM = 2 * STAGE_B;                   // 81920

    cudaFuncSetAttribute(k_mma_gemm, cudaFuncAttributeMaxDynamicSharedMemorySize, MSM);

    // graph structure (+ W split inside k_count; g_deg/g_state zero invariant)
    k_count<<<CB8, 256>>>(ei, Wl2, Wr2, Wl3, Wr3);
    k_scan<<<SB, 1024>>>();
    k_fill<<<CB8, 256>>>(ei);

    const int HH = HIDDEN * HIDDEN;

    // layer 1 (FFMA, K=16) -> h1 hi/lo
    k_agg16<<<WB, 256>>>(x);
    k_sage_gemm<<<GB, 256>>>(p_agg, x, Wl1, Wr1, b1, p_h1h, p_h1l, IN_DIM);

    // layer 2 (fp16 split HMMA, pipelined) -> h2 hi/lo
    k_agg128<<<WB, 256>>>(p_h1h, p_aggh, p_aggl);
    k_mma_gemm<<<GB, 256, MSM>>>(p_aggh, p_aggl, p_h1h, p_h1l,
                                 p_Whs + 0 * HH, p_Wls + 0 * HH,
                                 p_Whs + 1 * HH, p_Wls + 1 * HH,
                                 b2, p_h2h, p_h2l, nullptr, nullptr, nullptr, 0);

    // layer 3 (fp16 split HMMA, pipelined) + fused head -> out
    k_agg128<<<WB, 256>>>(p_h2h, p_aggh, p_aggl);
    k_mma_gemm<<<GB, 256, MSM>>>(p_aggh, p_aggl, p_h2h, p_h2l,
                                 p_Whs + 2 * HH, p_Wls + 2 * HH,
                                 p_Whs + 3 * HH, p_Wls + 3 * HH,
                                 b3, nullptr, nullptr, Wh, bh, out, 1);
}